// round 1
// baseline (speedup 1.0000x reference)
#include <cuda_runtime.h>

// Problem constants (fixed by the dataset shapes)
#define NCLS   19
#define NBINS  15
#define HW     (512 * 1024)          // 2^19
#define NB     4
#define NPIX   (NB * HW)             // 2,097,152 pixels
#define NCELLS (NCLS * NBINS)        // 285

// Global histogram of diff[c][b] = sum over pixels of (p_c - [label==c]) for
// pixels whose p_c falls in bin b.  Final answer = sum(|diff|) / (C*N).
__device__ float g_hist[NCELLS];

__global__ void zero_hist_kernel() {
    int i = blockIdx.x * blockDim.x + threadIdx.x;
    if (i < NCELLS) g_hist[i] = 0.0f;
}

__global__ __launch_bounds__(256)
void ece_main_kernel(const float* __restrict__ logits,
                     const int*   __restrict__ labels) {
    __shared__ float s_hist[NCELLS];
    for (int i = threadIdx.x; i < NCELLS; i += blockDim.x) s_hist[i] = 0.0f;
    __syncthreads();

    // Per-thread register accumulators for the two most common bins.
    float acc0[NCLS];
    float acc1[NCLS];
#pragma unroll
    for (int c = 0; c < NCLS; c++) { acc0[c] = 0.0f; acc1[c] = 0.0f; }

    const unsigned stride = gridDim.x * blockDim.x;
    for (unsigned i = blockIdx.x * blockDim.x + threadIdx.x; i < (unsigned)NPIX; i += stride) {
        const unsigned b  = i >> 19;          // HW = 2^19
        const unsigned hw = i & (HW - 1);
        const float* base = logits + (size_t)b * (NCLS * HW) + hw;

        // Load all 19 class logits (coalesced 128B per class-plane per warp,
        // 19-deep MLP).
        float x[NCLS];
#pragma unroll
        for (int c = 0; c < NCLS; c++) x[c] = __ldg(base + c * HW);
        const int lab = __ldg(labels + i);

        // Softmax (max-subtracted, fp32, fast exp).
        float m = x[0];
#pragma unroll
        for (int c = 1; c < NCLS; c++) m = fmaxf(m, x[c]);
        float S = 0.0f;
#pragma unroll
        for (int c = 0; c < NCLS; c++) { x[c] = __expf(x[c] - m); S += x[c]; }
        const float inv = 1.0f / S;

#pragma unroll
        for (int c = 0; c < NCLS; c++) {
            const float p = x[c] * inv;
            if (p > 0.0f) {                               // matches reference's conf>0 gate
                const float d = p - ((lab == c) ? 1.0f : 0.0f);
                // bin = clip(ceil(p*15) - 1, 0, 14); p>0 => ceil>=1 => bin>=0
                int bin = __float2int_ru(p * 15.0f) - 1;
                if (bin == 0)       acc0[c] += d;
                else if (bin == 1)  acc1[c] += d;
                else {
                    bin = min(bin, NBINS - 1);
                    atomicAdd(&s_hist[c * NBINS + bin], d);
                }
            }
        }
    }

    // One-time warp reduction of the register accumulators -> shared hist.
    const int lane = threadIdx.x & 31;
#pragma unroll
    for (int c = 0; c < NCLS; c++) {
        float v = acc0[c];
        v += __shfl_xor_sync(0xffffffffu, v, 16);
        v += __shfl_xor_sync(0xffffffffu, v, 8);
        v += __shfl_xor_sync(0xffffffffu, v, 4);
        v += __shfl_xor_sync(0xffffffffu, v, 2);
        v += __shfl_xor_sync(0xffffffffu, v, 1);
        float w = acc1[c];
        w += __shfl_xor_sync(0xffffffffu, w, 16);
        w += __shfl_xor_sync(0xffffffffu, w, 8);
        w += __shfl_xor_sync(0xffffffffu, w, 4);
        w += __shfl_xor_sync(0xffffffffu, w, 2);
        w += __shfl_xor_sync(0xffffffffu, w, 1);
        if (lane == 0) {
            atomicAdd(&s_hist[c * NBINS + 0], v);
            atomicAdd(&s_hist[c * NBINS + 1], w);
        }
    }
    __syncthreads();

    // Block flush -> global accumulators.
    for (int i = threadIdx.x; i < NCELLS; i += blockDim.x) {
        float v = s_hist[i];
        if (v != 0.0f) atomicAdd(&g_hist[i], v);
    }
}

__global__ void ece_finalize_kernel(float* __restrict__ out) {
    // Single warp: 285 cells.
    double v = 0.0;
    for (int i = threadIdx.x; i < NCELLS; i += 32) v += fabs((double)g_hist[i]);
#pragma unroll
    for (int s = 16; s > 0; s >>= 1)
        v += __shfl_xor_sync(0xffffffffu, v, s);
    if (threadIdx.x == 0)
        out[0] = (float)(v / ((double)NCLS * (double)NPIX));
}

extern "C" void kernel_launch(void* const* d_in, const int* in_sizes, int n_in,
                              void* d_out, int out_size) {
    // Inputs per metadata order: logits (fp32, 39,845,888 elems), labels (int32, 2,097,152).
    const float* logits;
    const int*   labels;
    if (in_sizes[0] == NPIX) {          // defensive: detect order by size
        labels = (const int*)d_in[0];
        logits = (const float*)d_in[1];
    } else {
        logits = (const float*)d_in[0];
        labels = (const int*)d_in[1];
    }
    float* out = (float*)d_out;

    zero_hist_kernel<<<1, 288>>>();
    ece_main_kernel<<<888, 256>>>(logits, labels);
    ece_finalize_kernel<<<1, 32>>>(out);
}